// round 2
// baseline (speedup 1.0000x reference)
#include <cuda_runtime.h>

typedef unsigned long long u64;

#define WB 8
#define NW 4
#define CTA_THREADS 128
#define TPTS 10
#define DDIM 32
#define NEXP 8

// ---- shared memory layout (float offsets) ----
#define SW1   0          // 33*64 = 2112
#define SB1   2112       // 64
#define SW2   2176       // 64*64 = 4096
#define SB2   6272       // 64
#define SW3   6336       // 64*32 = 2048
#define SB3   8384       // 32
#define SGW1  8416       // 64*64 = 4096
#define SGB1  12512      // 64
#define SGW2  12576      // 64*8 = 512
#define SGB2  13088      // 8
#define SACT  13096
// per-warp activation region: inp 264 | gin 512 | h 512 | f 2048
#define OFF_GIN 264
#define OFF_H   776
#define OFF_F   1288
#define WARP_ACT 3336
#define SMEM_BYTES ((SACT + NW * WARP_ACT) * 4)   // 105760 bytes

static __device__ __forceinline__ u64 pack2(float lo, float hi){
    u64 r; asm("mov.b64 %0,{%1,%2};" : "=l"(r) : "f"(lo), "f"(hi)); return r;
}
static __device__ __forceinline__ void unpack2(u64 v, float &lo, float &hi){
    asm("mov.b64 {%0,%1},%2;" : "=f"(lo), "=f"(hi) : "l"(v));
}
static __device__ __forceinline__ u64 ffma2(u64 a, u64 b, u64 c){
    u64 d; asm("fma.rn.f32x2 %0,%1,%2,%3;" : "=l"(d) : "l"(a), "l"(b), "l"(c)); return d;
}
// accurate fast tanh: 1 - 2/(exp(2x)+1), MUFU ex2+rcp, ~1e-6 rel err
static __device__ __forceinline__ float tanh_fast(float x){
    float e, r;
    asm("ex2.approx.f32 %0,%1;" : "=f"(e) : "f"(x * 2.8853900817779268f));
    asm("rcp.approx.f32 %0,%1;" : "=f"(r) : "f"(e + 1.0f));
    return fmaf(-2.0f, r, 1.0f);
}
static __device__ __forceinline__ float exp_fast(float x){
    float e; asm("ex2.approx.f32 %0,%1;" : "=f"(e) : "f"(x * 1.4426950408889634f)); return e;
}
static __device__ __forceinline__ float rcp_fast(float x){
    float r; asm("rcp.approx.f32 %0,%1;" : "=f"(r) : "f"(x)); return r;
}

static __device__ __forceinline__ void copy_f4(float* dst, const float* __restrict__ src,
                                               int n4, int tid){
    const float4* s = (const float4*)src;
    float4* d = (float4*)dst;
    for (int i = tid; i < n4; i += CTA_THREADS) d[i] = s[i];
}

// row-MAC: 8 f32x2 accumulators (cols lane / lane+32, batch pairs)
#define ROWMAC8(acc, rowptr, w0p, w1p) { \
    ulonglong2 a0_ = *(const ulonglong2*)(rowptr); \
    ulonglong2 a1_ = *(const ulonglong2*)((rowptr) + 4); \
    acc[0] = ffma2(w0p, a0_.x, acc[0]); acc[1] = ffma2(w0p, a0_.y, acc[1]); \
    acc[2] = ffma2(w0p, a1_.x, acc[2]); acc[3] = ffma2(w0p, a1_.y, acc[3]); \
    acc[4] = ffma2(w1p, a0_.x, acc[4]); acc[5] = ffma2(w1p, a0_.y, acc[5]); \
    acc[6] = ffma2(w1p, a1_.x, acc[6]); acc[7] = ffma2(w1p, a1_.y, acc[7]); }

__global__ void __launch_bounds__(CTA_THREADS, 2)
ameode_kernel(const float* __restrict__ x0,  const float* __restrict__ tspan,
              const float* __restrict__ gW1, const float* __restrict__ gb1,
              const float* __restrict__ gW2, const float* __restrict__ gb2,
              const float* __restrict__ gW3, const float* __restrict__ gb3,
              const float* __restrict__ gGw1, const float* __restrict__ gGb1,
              const float* __restrict__ gGw2, const float* __restrict__ gGb2,
              float* __restrict__ out)
{
    extern __shared__ float sm[];
    const int tid  = threadIdx.x;
    const int lane = tid & 31;
    const int warp = tid >> 5;
    const int bbase = blockIdx.x * (NW * WB) + warp * WB;

    // stage gating weights once (resident for whole kernel)
    copy_f4(sm + SGW1, gGw1, 1024, tid);
    copy_f4(sm + SGB1, gGb1,   16, tid);
    copy_f4(sm + SGW2, gGw2,  128, tid);
    copy_f4(sm + SGB2, gGb2,    2, tid);
    __syncthreads();

    float* sInp = sm + SACT + warp * WARP_ACT;   // [33][8]
    float* sGin = sInp + OFF_GIN;                // [64][8], reused for wgt[8][8]
    float* sH   = sInp + OFF_H;                  // [64][8]
    float* sF   = sInp + OFF_F;                  // [8][32][8]

    float x[WB], xin[WB], ksum[WB];
    #pragma unroll
    for (int wb = 0; wb < WB; wb++){
        x[wb] = x0[(bbase + wb) * DDIM + lane];
        out[(bbase + wb) * (TPTS * DDIM) + lane] = x[wb];   // t = 0 row
    }

    #pragma unroll 1
    for (int s = 0; s < TPTS - 1; s++){
        const float t0 = tspan[s], t1 = tspan[s + 1];
        const float dt = t1 - t0;
        #pragma unroll
        for (int wb = 0; wb < WB; wb++){ xin[wb] = x[wb]; ksum[wb] = 0.f; }

        #pragma unroll 1
        for (int sub = 0; sub < 4; sub++){
            const float cc   = (sub == 0) ? 0.f : ((sub == 3) ? 1.f : 0.5f);
            const float tcur = fmaf(cc, dt, t0);

            // =================== dyn(tcur, xin) -> k ===================
            __syncwarp();
            *(float4*)(sInp + lane * 8)     = make_float4(xin[0], xin[1], xin[2], xin[3]);
            *(float4*)(sInp + lane * 8 + 4) = make_float4(xin[4], xin[5], xin[6], xin[7]);
            if (lane == 0){
                float4 tv = make_float4(tcur, tcur, tcur, tcur);
                *(float4*)(sInp + 32 * 8)     = tv;
                *(float4*)(sInp + 32 * 8 + 4) = tv;
            }
            __syncwarp();

            float dx[WB];
            #pragma unroll
            for (int wb = 0; wb < WB; wb++) dx[wb] = 0.f;

            #pragma unroll 1
            for (int e = 0; e < NEXP; e++){
                __syncthreads();   // all warps done with previous expert's weights
                copy_f4(sm + SW1, gW1 + e * 2112, 528, tid);
                copy_f4(sm + SB1, gb1 + e * 64,    16, tid);
                copy_f4(sm + SW2, gW2 + e * 4096, 1024, tid);
                copy_f4(sm + SB2, gb2 + e * 64,    16, tid);
                copy_f4(sm + SW3, gW3 + e * 2048,  512, tid);
                copy_f4(sm + SB3, gb3 + e * 32,     8, tid);
                __syncthreads();

                // ---- L1: h = tanh(inp @ W1e + b1e); lane owns cols lane, lane+32
                {
                    u64 acc[8];
                    #pragma unroll
                    for (int p = 0; p < 8; p++) acc[p] = 0ull;
                    #pragma unroll 4
                    for (int i = 0; i < 33; i++){
                        float w0 = sm[SW1 + i * 64 + lane];
                        float w1 = sm[SW1 + i * 64 + 32 + lane];
                        u64 w0p = pack2(w0, w0), w1p = pack2(w1, w1);
                        ROWMAC8(acc, sInp + i * 8, w0p, w1p);
                    }
                    float bl = sm[SB1 + lane], bh = sm[SB1 + 32 + lane];
                    float hv[16];
                    #pragma unroll
                    for (int p = 0; p < 4; p++){
                        float lo, hi;
                        unpack2(acc[p], lo, hi);
                        hv[2*p]     = tanh_fast(lo + bl); hv[2*p+1]   = tanh_fast(hi + bl);
                        unpack2(acc[4+p], lo, hi);
                        hv[8+2*p]   = tanh_fast(lo + bh); hv[8+2*p+1] = tanh_fast(hi + bh);
                    }
                    __syncwarp();
                    *(float4*)(sH + lane * 8)            = make_float4(hv[0], hv[1], hv[2], hv[3]);
                    *(float4*)(sH + lane * 8 + 4)        = make_float4(hv[4], hv[5], hv[6], hv[7]);
                    *(float4*)(sH + (lane + 32) * 8)     = make_float4(hv[8], hv[9], hv[10], hv[11]);
                    *(float4*)(sH + (lane + 32) * 8 + 4) = make_float4(hv[12], hv[13], hv[14], hv[15]);
                    __syncwarp();
                }

                // ---- L2: h = tanh(h @ W2e + b2e) (in-place via reg staging)
                {
                    u64 acc[8];
                    #pragma unroll
                    for (int p = 0; p < 8; p++) acc[p] = 0ull;
                    #pragma unroll 4
                    for (int i = 0; i < 64; i++){
                        float w0 = sm[SW2 + i * 64 + lane];
                        float w1 = sm[SW2 + i * 64 + 32 + lane];
                        u64 w0p = pack2(w0, w0), w1p = pack2(w1, w1);
                        ROWMAC8(acc, sH + i * 8, w0p, w1p);
                    }
                    float bl = sm[SB2 + lane], bh = sm[SB2 + 32 + lane];
                    float hv[16];
                    #pragma unroll
                    for (int p = 0; p < 4; p++){
                        float lo, hi;
                        unpack2(acc[p], lo, hi);
                        hv[2*p]     = tanh_fast(lo + bl); hv[2*p+1]   = tanh_fast(hi + bl);
                        unpack2(acc[4+p], lo, hi);
                        hv[8+2*p]   = tanh_fast(lo + bh); hv[8+2*p+1] = tanh_fast(hi + bh);
                    }
                    __syncwarp();   // all lanes done reading sH
                    *(float4*)(sH + lane * 8)            = make_float4(hv[0], hv[1], hv[2], hv[3]);
                    *(float4*)(sH + lane * 8 + 4)        = make_float4(hv[4], hv[5], hv[6], hv[7]);
                    *(float4*)(sH + (lane + 32) * 8)     = make_float4(hv[8], hv[9], hv[10], hv[11]);
                    *(float4*)(sH + (lane + 32) * 8 + 4) = make_float4(hv[12], hv[13], hv[14], hv[15]);
                    __syncwarp();
                }

                // ---- L3: f = h @ W3e + b3e ; lane owns col d = lane
                {
                    u64 a3[4];
                    #pragma unroll
                    for (int p = 0; p < 4; p++) a3[p] = 0ull;
                    #pragma unroll 4
                    for (int kk = 0; kk < 64; kk++){
                        float w = sm[SW3 + kk * 32 + lane];
                        u64 wp = pack2(w, w);
                        ulonglong2 a0 = *(const ulonglong2*)(sH + kk * 8);
                        ulonglong2 a1 = *(const ulonglong2*)(sH + kk * 8 + 4);
                        a3[0] = ffma2(wp, a0.x, a3[0]); a3[1] = ffma2(wp, a0.y, a3[1]);
                        a3[2] = ffma2(wp, a1.x, a3[2]); a3[3] = ffma2(wp, a1.y, a3[3]);
                    }
                    float b3v = sm[SB3 + lane];
                    float fv[8];
                    #pragma unroll
                    for (int p = 0; p < 4; p++){
                        float lo, hi; unpack2(a3[p], lo, hi);
                        fv[2*p] = lo + b3v; fv[2*p+1] = hi + b3v;
                    }
                    *(float4*)(sF + e * 256 + lane * 8)     = make_float4(fv[0], fv[1], fv[2], fv[3]);
                    *(float4*)(sF + e * 256 + lane * 8 + 4) = make_float4(fv[4], fv[5], fv[6], fv[7]);
                    #pragma unroll
                    for (int wb = 0; wb < WB; wb++) dx[wb] += fv[wb];
                }
            } // expert loop

            // ---- gating: gin = concat(xin, mean_e f) ----
            *(float4*)(sGin + lane * 8)            = make_float4(xin[0], xin[1], xin[2], xin[3]);
            *(float4*)(sGin + lane * 8 + 4)        = make_float4(xin[4], xin[5], xin[6], xin[7]);
            *(float4*)(sGin + (lane + 32) * 8)     = make_float4(dx[0]*0.125f, dx[1]*0.125f, dx[2]*0.125f, dx[3]*0.125f);
            *(float4*)(sGin + (lane + 32) * 8 + 4) = make_float4(dx[4]*0.125f, dx[5]*0.125f, dx[6]*0.125f, dx[7]*0.125f);
            __syncwarp();
            {
                u64 ag[8];
                #pragma unroll
                for (int p = 0; p < 8; p++) ag[p] = 0ull;
                #pragma unroll 4
                for (int i = 0; i < 64; i++){
                    float w0 = sm[SGW1 + i * 64 + lane];
                    float w1 = sm[SGW1 + i * 64 + 32 + lane];
                    u64 w0p = pack2(w0, w0), w1p = pack2(w1, w1);
                    ROWMAC8(ag, sGin + i * 8, w0p, w1p);
                }
                float bl = sm[SGB1 + lane], bh = sm[SGB1 + 32 + lane];
                float gv[16];
                #pragma unroll
                for (int p = 0; p < 4; p++){
                    float lo, hi;
                    unpack2(ag[p], lo, hi);
                    gv[2*p]     = tanh_fast(lo + bl); gv[2*p+1]   = tanh_fast(hi + bl);
                    unpack2(ag[4+p], lo, hi);
                    gv[8+2*p]   = tanh_fast(lo + bh); gv[8+2*p+1] = tanh_fast(hi + bh);
                }
                __syncwarp();
                *(float4*)(sH + lane * 8)            = make_float4(gv[0], gv[1], gv[2], gv[3]);
                *(float4*)(sH + lane * 8 + 4)        = make_float4(gv[4], gv[5], gv[6], gv[7]);
                *(float4*)(sH + (lane + 32) * 8)     = make_float4(gv[8], gv[9], gv[10], gv[11]);
                *(float4*)(sH + (lane + 32) * 8 + 4) = make_float4(gv[12], gv[13], gv[14], gv[15]);
                __syncwarp();
            }
            // ---- logits + softmax: lane computes expert ep over quarter q of H
            float wgt[8];
            {
                const int ep = lane & 7, q = lane >> 3;
                u64 z2[4];
                #pragma unroll
                for (int p = 0; p < 4; p++) z2[p] = 0ull;
                #pragma unroll 4
                for (int r = 0; r < 16; r++){
                    int j = q * 16 + r;
                    float w = sm[SGW2 + j * 8 + ep];
                    u64 wp = pack2(w, w);
                    ulonglong2 a0 = *(const ulonglong2*)(sH + j * 8);
                    ulonglong2 a1 = *(const ulonglong2*)(sH + j * 8 + 4);
                    z2[0] = ffma2(wp, a0.x, z2[0]); z2[1] = ffma2(wp, a0.y, z2[1]);
                    z2[2] = ffma2(wp, a1.x, z2[2]); z2[3] = ffma2(wp, a1.y, z2[3]);
                }
                float z[8];
                #pragma unroll
                for (int p = 0; p < 4; p++){ unpack2(z2[p], z[2*p], z[2*p+1]); }
                float gb2v = sm[SGB2 + ep];
                #pragma unroll
                for (int v = 0; v < 8; v++){
                    // reduce partials across quarters (bits 3,4)
                    z[v] += __shfl_xor_sync(0xffffffffu, z[v], 8);
                    z[v] += __shfl_xor_sync(0xffffffffu, z[v], 16);
                    z[v] += gb2v;
                    // softmax across experts (bits 0..2)
                    float m = z[v];
                    m = fmaxf(m, __shfl_xor_sync(0xffffffffu, m, 1));
                    m = fmaxf(m, __shfl_xor_sync(0xffffffffu, m, 2));
                    m = fmaxf(m, __shfl_xor_sync(0xffffffffu, m, 4));
                    float p = exp_fast(z[v] - m);
                    float ss = p;
                    ss += __shfl_xor_sync(0xffffffffu, ss, 1);
                    ss += __shfl_xor_sync(0xffffffffu, ss, 2);
                    ss += __shfl_xor_sync(0xffffffffu, ss, 4);
                    wgt[v] = p * rcp_fast(ss);
                }
            }
            if (lane < 8){   // q==0 lanes publish wgt[e=lane][wb]
                *(float4*)(sGin + lane * 8)     = make_float4(wgt[0], wgt[1], wgt[2], wgt[3]);
                *(float4*)(sGin + lane * 8 + 4) = make_float4(wgt[4], wgt[5], wgt[6], wgt[7]);
            }
            __syncwarp();

            // ---- k = sum_e wgt[e] * f[e] (lane reads only its own sF rows)
            float k[WB];
            #pragma unroll
            for (int wb = 0; wb < WB; wb++) k[wb] = 0.f;
            #pragma unroll
            for (int e2 = 0; e2 < NEXP; e2++){
                float4 wa = *(const float4*)(sGin + e2 * 8);
                float4 wv = *(const float4*)(sGin + e2 * 8 + 4);
                float4 fa = *(const float4*)(sF + e2 * 256 + lane * 8);
                float4 fb = *(const float4*)(sF + e2 * 256 + lane * 8 + 4);
                k[0] = fmaf(wa.x, fa.x, k[0]); k[1] = fmaf(wa.y, fa.y, k[1]);
                k[2] = fmaf(wa.z, fa.z, k[2]); k[3] = fmaf(wa.w, fa.w, k[3]);
                k[4] = fmaf(wv.x, fb.x, k[4]); k[5] = fmaf(wv.y, fb.y, k[5]);
                k[6] = fmaf(wv.z, fb.z, k[6]); k[7] = fmaf(wv.w, fb.w, k[7]);
            }
            // =================== end dyn ===================

            const float wsum = (sub == 0 || sub == 3) ? 1.f : 2.f;
            #pragma unroll
            for (int wb = 0; wb < WB; wb++) ksum[wb] = fmaf(wsum, k[wb], ksum[wb]);
            if (sub < 3){
                const float nc = (sub == 2) ? dt : 0.5f * dt;
                #pragma unroll
                for (int wb = 0; wb < WB; wb++) xin[wb] = fmaf(nc, k[wb], x[wb]);
            }
        } // sub

        const float sc = dt * (1.0f / 6.0f);
        #pragma unroll
        for (int wb = 0; wb < WB; wb++){
            x[wb] = fmaf(sc, ksum[wb], x[wb]);
            out[(bbase + wb) * (TPTS * DDIM) + (s + 1) * DDIM + lane] = x[wb];
        }
    } // step
}

extern "C" void kernel_launch(void* const* d_in, const int* in_sizes, int n_in,
                              void* d_out, int out_size)
{
    (void)in_sizes; (void)n_in; (void)out_size;
    cudaFuncSetAttribute(ameode_kernel, cudaFuncAttributeMaxDynamicSharedMemorySize, SMEM_BYTES);
    ameode_kernel<<<512, CTA_THREADS, SMEM_BYTES>>>(
        (const float*)d_in[0],  (const float*)d_in[1],
        (const float*)d_in[2],  (const float*)d_in[3],
        (const float*)d_in[4],  (const float*)d_in[5],
        (const float*)d_in[6],  (const float*)d_in[7],
        (const float*)d_in[8],  (const float*)d_in[9],
        (const float*)d_in[10], (const float*)d_in[11],
        (float*)d_out);
}

// round 4
// speedup vs baseline: 1.1752x; 1.1752x over previous
#include <cuda_runtime.h>

typedef unsigned long long u64;
typedef unsigned int u32;

#define WB 4
#define NW 8
#define CTA_THREADS 256
#define TPTS 10
#define DDIM 32
#define NEXP 8

// ---- shared memory layout (float offsets) ----
#define SW1   0          // 33*64 = 2112
#define SB1   2112       // 64
#define SW2   2176       // 64*64 = 4096
#define SB2   6272       // 64
#define SW3   6336       // 64*32 = 2048
#define SB3   8384       // 32
#define SGW1  8416       // 64*64 = 4096
#define SGB1  12512      // 64
#define SGW2  12576      // 64*8 = 512
#define SGB2  13088      // 8
#define SACT  13096
// per-warp activation region (WB=4): inp 132 | gin 256 | h 256 | f 1024
#define OFF_GIN 132
#define OFF_H   388
#define OFF_F   644
#define WARP_ACT 1668
#define SMEM_BYTES ((SACT + NW * WARP_ACT) * 4)   // 105760 bytes -> 2 CTAs/SM

static __device__ __forceinline__ u64 pack2(float lo, float hi){
    u64 r; asm("mov.b64 %0,{%1,%2};" : "=l"(r) : "f"(lo), "f"(hi)); return r;
}
static __device__ __forceinline__ void unpack2(u64 v, float &lo, float &hi){
    asm("mov.b64 {%0,%1},%2;" : "=f"(lo), "=f"(hi) : "l"(v));
}
static __device__ __forceinline__ u64 ffma2(u64 a, u64 b, u64 c){
    u64 d; asm("fma.rn.f32x2 %0,%1,%2,%3;" : "=l"(d) : "l"(a), "l"(b), "l"(c)); return d;
}
// accurate fast tanh: 1 - 2/(exp(2x)+1), MUFU ex2+rcp, ~1e-6 rel err
static __device__ __forceinline__ float tanh_fast(float x){
    float e, r;
    asm("ex2.approx.f32 %0,%1;" : "=f"(e) : "f"(x * 2.8853900817779268f));
    asm("rcp.approx.f32 %0,%1;" : "=f"(r) : "f"(e + 1.0f));
    return fmaf(-2.0f, r, 1.0f);
}
static __device__ __forceinline__ float exp_fast(float x){
    float e; asm("ex2.approx.f32 %0,%1;" : "=f"(e) : "f"(x * 1.4426950408889634f)); return e;
}
static __device__ __forceinline__ float rcp_fast(float x){
    float r; asm("rcp.approx.f32 %0,%1;" : "=f"(r) : "f"(x)); return r;
}

static __device__ __forceinline__ void cp16(u32 dst_smem, const float4* src){
    asm volatile("cp.async.cg.shared.global [%0],[%1],16;" :: "r"(dst_smem), "l"(src));
}
// async staged copy: n4 float4s
static __device__ __forceinline__ void copy_async(float* dst, const float* __restrict__ src,
                                                  int n4, int tid){
    u32 d = (u32)__cvta_generic_to_shared(dst);
    const float4* s = (const float4*)src;
    for (int i = tid; i < n4; i += CTA_THREADS) cp16(d + i * 16, s + i);
}
static __device__ __forceinline__ void copy_f4(float* dst, const float* __restrict__ src,
                                               int n4, int tid){
    const float4* s = (const float4*)src;
    float4* d = (float4*)dst;
    for (int i = tid; i < n4; i += CTA_THREADS) d[i] = s[i];
}

// row-MAC (WB=4): 4 f32x2 accumulators (cols lane / lane+32, 2 batch pairs)
#define ROWMAC4(acc, rowptr, w0p, w1p) { \
    ulonglong2 a_ = *(const ulonglong2*)(rowptr); \
    acc[0] = ffma2(w0p, a_.x, acc[0]); acc[1] = ffma2(w0p, a_.y, acc[1]); \
    acc[2] = ffma2(w1p, a_.x, acc[2]); acc[3] = ffma2(w1p, a_.y, acc[3]); }

__global__ void __launch_bounds__(CTA_THREADS, 2)
ameode_kernel(const float* __restrict__ x0,  const float* __restrict__ tspan,
              const float* __restrict__ gW1, const float* __restrict__ gb1,
              const float* __restrict__ gW2, const float* __restrict__ gb2,
              const float* __restrict__ gW3, const float* __restrict__ gb3,
              const float* __restrict__ gGw1, const float* __restrict__ gGb1,
              const float* __restrict__ gGw2, const float* __restrict__ gGb2,
              float* __restrict__ out)
{
    extern __shared__ float sm[];
    const int tid  = threadIdx.x;
    const int lane = tid & 31;
    const int warp = tid >> 5;
    const int bbase = blockIdx.x * (NW * WB) + warp * WB;

    // stage gating weights once (resident for whole kernel)
    copy_f4(sm + SGW1, gGw1, 1024, tid);
    copy_f4(sm + SGB1, gGb1,   16, tid);
    copy_f4(sm + SGW2, gGw2,  128, tid);
    copy_f4(sm + SGB2, gGb2,    2, tid);
    __syncthreads();

    float* sInp = sm + SACT + warp * WARP_ACT;   // [33][4]
    float* sGin = sInp + OFF_GIN;                // [64][4], reused for wgt[8][4]
    float* sH   = sInp + OFF_H;                  // [64][4]
    float* sF   = sInp + OFF_F;                  // [8][32][4]

    float x[WB], xin[WB], ksum[WB];
    #pragma unroll
    for (int wb = 0; wb < WB; wb++){
        x[wb] = x0[(bbase + wb) * DDIM + lane];
        out[(bbase + wb) * (TPTS * DDIM) + lane] = x[wb];   // t = 0 row
    }

    #pragma unroll 1
    for (int s = 0; s < TPTS - 1; s++){
        const float t0 = tspan[s], t1 = tspan[s + 1];
        const float dt = t1 - t0;
        #pragma unroll
        for (int wb = 0; wb < WB; wb++){ xin[wb] = x[wb]; ksum[wb] = 0.f; }

        #pragma unroll 1
        for (int sub = 0; sub < 4; sub++){
            const float cc   = (sub == 0) ? 0.f : ((sub == 3) ? 1.f : 0.5f);
            const float tcur = fmaf(cc, dt, t0);

            // =================== dyn(tcur, xin) -> k ===================
            __syncwarp();
            *(float4*)(sInp + lane * 4) = make_float4(xin[0], xin[1], xin[2], xin[3]);
            if (lane == 0)
                *(float4*)(sInp + 32 * 4) = make_float4(tcur, tcur, tcur, tcur);
            __syncwarp();

            float dx[WB];
            #pragma unroll
            for (int wb = 0; wb < WB; wb++) dx[wb] = 0.f;

            #pragma unroll 1
            for (int e = 0; e < NEXP; e++){
                __syncthreads();   // all warps done with previous expert's weights
                copy_async(sm + SW1, gW1 + e * 2112, 528, tid);
                copy_async(sm + SB1, gb1 + e * 64,    16, tid);
                copy_async(sm + SW2, gW2 + e * 4096, 1024, tid);
                copy_async(sm + SB2, gb2 + e * 64,    16, tid);
                copy_async(sm + SW3, gW3 + e * 2048,  512, tid);
                copy_async(sm + SB3, gb3 + e * 32,     8, tid);
                asm volatile("cp.async.commit_group;");
                asm volatile("cp.async.wait_group 0;");
                __syncthreads();

                // ---- L1: h = tanh(inp @ W1e + b1e); lane owns cols lane, lane+32
                {
                    u64 acc[4];
                    #pragma unroll
                    for (int p = 0; p < 4; p++) acc[p] = 0ull;
                    #pragma unroll 4
                    for (int i = 0; i < 33; i++){
                        float w0 = sm[SW1 + i * 64 + lane];
                        float w1 = sm[SW1 + i * 64 + 32 + lane];
                        u64 w0p = pack2(w0, w0), w1p = pack2(w1, w1);
                        ROWMAC4(acc, sInp + i * 4, w0p, w1p);
                    }
                    float bl = sm[SB1 + lane], bh = sm[SB1 + 32 + lane];
                    float hv[8];
                    #pragma unroll
                    for (int p = 0; p < 2; p++){
                        float lo, hi;
                        unpack2(acc[p], lo, hi);
                        hv[2*p]     = tanh_fast(lo + bl); hv[2*p+1]   = tanh_fast(hi + bl);
                        unpack2(acc[2+p], lo, hi);
                        hv[4+2*p]   = tanh_fast(lo + bh); hv[4+2*p+1] = tanh_fast(hi + bh);
                    }
                    __syncwarp();
                    *(float4*)(sH + lane * 4)        = make_float4(hv[0], hv[1], hv[2], hv[3]);
                    *(float4*)(sH + (lane + 32) * 4) = make_float4(hv[4], hv[5], hv[6], hv[7]);
                    __syncwarp();
                }

                // ---- L2: h = tanh(h @ W2e + b2e)
                {
                    u64 acc[4];
                    #pragma unroll
                    for (int p = 0; p < 4; p++) acc[p] = 0ull;
                    #pragma unroll 4
                    for (int i = 0; i < 64; i++){
                        float w0 = sm[SW2 + i * 64 + lane];
                        float w1 = sm[SW2 + i * 64 + 32 + lane];
                        u64 w0p = pack2(w0, w0), w1p = pack2(w1, w1);
                        ROWMAC4(acc, sH + i * 4, w0p, w1p);
                    }
                    float bl = sm[SB2 + lane], bh = sm[SB2 + 32 + lane];
                    float hv[8];
                    #pragma unroll
                    for (int p = 0; p < 2; p++){
                        float lo, hi;
                        unpack2(acc[p], lo, hi);
                        hv[2*p]     = tanh_fast(lo + bl); hv[2*p+1]   = tanh_fast(hi + bl);
                        unpack2(acc[2+p], lo, hi);
                        hv[4+2*p]   = tanh_fast(lo + bh); hv[4+2*p+1] = tanh_fast(hi + bh);
                    }
                    __syncwarp();   // all lanes done reading sH
                    *(float4*)(sH + lane * 4)        = make_float4(hv[0], hv[1], hv[2], hv[3]);
                    *(float4*)(sH + (lane + 32) * 4) = make_float4(hv[4], hv[5], hv[6], hv[7]);
                    __syncwarp();
                }

                // ---- L3: f = h @ W3e + b3e ; lane owns col d = lane
                {
                    u64 a3[2];
                    a3[0] = 0ull; a3[1] = 0ull;
                    #pragma unroll 4
                    for (int kk = 0; kk < 64; kk++){
                        float w = sm[SW3 + kk * 32 + lane];
                        u64 wp = pack2(w, w);
                        ulonglong2 a = *(const ulonglong2*)(sH + kk * 4);
                        a3[0] = ffma2(wp, a.x, a3[0]); a3[1] = ffma2(wp, a.y, a3[1]);
                    }
                    float b3v = sm[SB3 + lane];
                    float fv[4];
                    float lo, hi;
                    unpack2(a3[0], lo, hi); fv[0] = lo + b3v; fv[1] = hi + b3v;
                    unpack2(a3[1], lo, hi); fv[2] = lo + b3v; fv[3] = hi + b3v;
                    *(float4*)(sF + e * 128 + lane * 4) = make_float4(fv[0], fv[1], fv[2], fv[3]);
                    #pragma unroll
                    for (int wb = 0; wb < WB; wb++) dx[wb] += fv[wb];
                }
            } // expert loop

            // ---- gating: gin = concat(xin, mean_e f) ----
            *(float4*)(sGin + lane * 4)        = make_float4(xin[0], xin[1], xin[2], xin[3]);
            *(float4*)(sGin + (lane + 32) * 4) = make_float4(dx[0]*0.125f, dx[1]*0.125f,
                                                             dx[2]*0.125f, dx[3]*0.125f);
            __syncwarp();
            {
                u64 ag[4];
                #pragma unroll
                for (int p = 0; p < 4; p++) ag[p] = 0ull;
                #pragma unroll 4
                for (int i = 0; i < 64; i++){
                    float w0 = sm[SGW1 + i * 64 + lane];
                    float w1 = sm[SGW1 + i * 64 + 32 + lane];
                    u64 w0p = pack2(w0, w0), w1p = pack2(w1, w1);
                    ROWMAC4(ag, sGin + i * 4, w0p, w1p);
                }
                float bl = sm[SGB1 + lane], bh = sm[SGB1 + 32 + lane];
                float gv[8];
                #pragma unroll
                for (int p = 0; p < 2; p++){
                    float lo, hi;
                    unpack2(ag[p], lo, hi);
                    gv[2*p]     = tanh_fast(lo + bl); gv[2*p+1]   = tanh_fast(hi + bl);
                    unpack2(ag[2+p], lo, hi);
                    gv[4+2*p]   = tanh_fast(lo + bh); gv[4+2*p+1] = tanh_fast(hi + bh);
                }
                __syncwarp();
                *(float4*)(sH + lane * 4)        = make_float4(gv[0], gv[1], gv[2], gv[3]);
                *(float4*)(sH + (lane + 32) * 4) = make_float4(gv[4], gv[5], gv[6], gv[7]);
                __syncwarp();
            }
            // ---- logits + softmax: lane = expert ep x quarter q of H
            float wgt[WB];
            {
                const int ep = lane & 7, q = lane >> 3;
                u64 z2[2];
                z2[0] = 0ull; z2[1] = 0ull;
                #pragma unroll 4
                for (int r = 0; r < 16; r++){
                    int j = q * 16 + r;
                    float w = sm[SGW2 + j * 8 + ep];
                    u64 wp = pack2(w, w);
                    ulonglong2 a = *(const ulonglong2*)(sH + j * 4);
                    z2[0] = ffma2(wp, a.x, z2[0]); z2[1] = ffma2(wp, a.y, z2[1]);
                }
                float z[WB];
                unpack2(z2[0], z[0], z[1]);
                unpack2(z2[1], z[2], z[3]);
                float gb2v = sm[SGB2 + ep];
                #pragma unroll
                for (int v = 0; v < WB; v++){
                    // reduce partials across quarters (bits 3,4)
                    z[v] += __shfl_xor_sync(0xffffffffu, z[v], 8);
                    z[v] += __shfl_xor_sync(0xffffffffu, z[v], 16);
                    z[v] += gb2v;
                    // softmax across experts (bits 0..2)
                    float m = z[v];
                    m = fmaxf(m, __shfl_xor_sync(0xffffffffu, m, 1));
                    m = fmaxf(m, __shfl_xor_sync(0xffffffffu, m, 2));
                    m = fmaxf(m, __shfl_xor_sync(0xffffffffu, m, 4));
                    float p = exp_fast(z[v] - m);
                    float ss = p;
                    ss += __shfl_xor_sync(0xffffffffu, ss, 1);
                    ss += __shfl_xor_sync(0xffffffffu, ss, 2);
                    ss += __shfl_xor_sync(0xffffffffu, ss, 4);
                    wgt[v] = p * rcp_fast(ss);
                }
            }
            if (lane < 8)   // q==0 lanes publish wgt[e=lane][wb]
                *(float4*)(sGin + lane * 4) = make_float4(wgt[0], wgt[1], wgt[2], wgt[3]);
            __syncwarp();

            // ---- k = sum_e wgt[e] * f[e]
            float k[WB];
            #pragma unroll
            for (int wb = 0; wb < WB; wb++) k[wb] = 0.f;
            #pragma unroll
            for (int e2 = 0; e2 < NEXP; e2++){
                float4 wa = *(const float4*)(sGin + e2 * 4);
                float4 fa = *(const float4*)(sF + e2 * 128 + lane * 4);
                k[0] = fmaf(wa.x, fa.x, k[0]); k[1] = fmaf(wa.y, fa.y, k[1]);
                k[2] = fmaf(wa.z, fa.z, k[2]); k[3] = fmaf(wa.w, fa.w, k[3]);
            }
            // =================== end dyn ===================

            const float wsum = (sub == 0 || sub == 3) ? 1.f : 2.f;
            #pragma unroll
            for (int wb = 0; wb < WB; wb++) ksum[wb] = fmaf(wsum, k[wb], ksum[wb]);
            if (sub < 3){
                const float nc = (sub == 2) ? dt : 0.5f * dt;
                #pragma unroll
                for (int wb = 0; wb < WB; wb++) xin[wb] = fmaf(nc, k[wb], x[wb]);
            }
        } // sub

        const float sc = dt * (1.0f / 6.0f);
        #pragma unroll
        for (int wb = 0; wb < WB; wb++){
            x[wb] = fmaf(sc, ksum[wb], x[wb]);
            out[(bbase + wb) * (TPTS * DDIM) + (s + 1) * DDIM + lane] = x[wb];
        }
    } // step
}

extern "C" void kernel_launch(void* const* d_in, const int* in_sizes, int n_in,
                              void* d_out, int out_size)
{
    (void)in_sizes; (void)n_in; (void)out_size;
    cudaFuncSetAttribute(ameode_kernel, cudaFuncAttributeMaxDynamicSharedMemorySize, SMEM_BYTES);
    ameode_kernel<<<512, CTA_THREADS, SMEM_BYTES>>>(
        (const float*)d_in[0],  (const float*)d_in[1],
        (const float*)d_in[2],  (const float*)d_in[3],
        (const float*)d_in[4],  (const float*)d_in[5],
        (const float*)d_in[6],  (const float*)d_in[7],
        (const float*)d_in[8],  (const float*)d_in[9],
        (const float*)d_in[10], (const float*)d_in[11],
        (float*)d_out);
}

// round 6
// speedup vs baseline: 1.4088x; 1.1988x over previous
#include <cuda_runtime.h>
#include <cuda_fp16.h>

typedef unsigned long long u64;
typedef unsigned int u32;

#define WB 8
#define NW 8
#define CTA_THREADS 256
#define TPTS 10
#define DDIM 32
#define NEXP 8

// ---- shared memory layout (float offsets) ----
#define SW1   0          // 33*64 = 2112
#define SB1   2112       // 64
#define SW2   2176       // 64*64 = 4096
#define SB2   6272       // 64
#define SW3   6336       // 64*32 = 2048
#define SB3   8384       // 32
#define SGW1  8416       // 64*64 = 4096
#define SGB1  12512      // 64
#define SGW2  12576      // 64*8 = 512
#define SGB2  13088      // 8
#define SACT  13096
// per-warp activation region (WB=8): inp 264 | hbuf 512 | f(half) 1024 float-equiv
#define OFF_H   264
#define OFF_F   776
#define WARP_ACT 1800    // floats = 7200 bytes
#define SMEM_BYTES ((SACT + NW * WARP_ACT) * 4)   // 109984 bytes -> 2 CTAs/SM

static __device__ __forceinline__ u64 pack2(float lo, float hi){
    u64 r; asm("mov.b64 %0,{%1,%2};" : "=l"(r) : "f"(lo), "f"(hi)); return r;
}
static __device__ __forceinline__ void unpack2(u64 v, float &lo, float &hi){
    asm("mov.b64 {%0,%1},%2;" : "=f"(lo), "=f"(hi) : "l"(v));
}
static __device__ __forceinline__ u64 ffma2(u64 a, u64 b, u64 c){
    u64 d; asm("fma.rn.f32x2 %0,%1,%2,%3;" : "=l"(d) : "l"(a), "l"(b), "l"(c)); return d;
}
// accurate fast tanh: 1 - 2/(exp(2x)+1), MUFU ex2+rcp, ~1e-6 rel err
static __device__ __forceinline__ float tanh_fast(float x){
    float e, r;
    asm("ex2.approx.f32 %0,%1;" : "=f"(e) : "f"(x * 2.8853900817779268f));
    asm("rcp.approx.f32 %0,%1;" : "=f"(r) : "f"(e + 1.0f));
    return fmaf(-2.0f, r, 1.0f);
}
static __device__ __forceinline__ float exp_fast(float x){
    float e; asm("ex2.approx.f32 %0,%1;" : "=f"(e) : "f"(x * 1.4426950408889634f)); return e;
}
static __device__ __forceinline__ float rcp_fast(float x){
    float r; asm("rcp.approx.f32 %0,%1;" : "=f"(r) : "f"(x)); return r;
}

static __device__ __forceinline__ void cp16(u32 dst_smem, const float4* src){
    asm volatile("cp.async.cg.shared.global [%0],[%1],16;" :: "r"(dst_smem), "l"(src));
}
static __device__ __forceinline__ void copy_async(float* dst, const float* __restrict__ src,
                                                  int n4, int tid){
    u32 d = (u32)__cvta_generic_to_shared(dst);
    const float4* s = (const float4*)src;
    for (int i = tid; i < n4; i += CTA_THREADS) cp16(d + i * 16, s + i);
}
static __device__ __forceinline__ void copy_f4(float* dst, const float* __restrict__ src,
                                               int n4, int tid){
    const float4* s = (const float4*)src;
    float4* d = (float4*)dst;
    for (int i = tid; i < n4; i += CTA_THREADS) d[i] = s[i];
}

// row-MAC (WB=8): 8 f32x2 accumulators (cols lane / lane+32, 4 batch pairs)
#define ROWMAC8(acc, rowptr, w0p, w1p) { \
    ulonglong2 a0_ = *(const ulonglong2*)(rowptr); \
    ulonglong2 a1_ = *(const ulonglong2*)((rowptr) + 4); \
    acc[0] = ffma2(w0p, a0_.x, acc[0]); acc[1] = ffma2(w0p, a0_.y, acc[1]); \
    acc[2] = ffma2(w0p, a1_.x, acc[2]); acc[3] = ffma2(w0p, a1_.y, acc[3]); \
    acc[4] = ffma2(w1p, a0_.x, acc[4]); acc[5] = ffma2(w1p, a0_.y, acc[5]); \
    acc[6] = ffma2(w1p, a1_.x, acc[6]); acc[7] = ffma2(w1p, a1_.y, acc[7]); }

__global__ void __launch_bounds__(CTA_THREADS, 2)
ameode_kernel(const float* __restrict__ x0,  const float* __restrict__ tspan,
              const float* __restrict__ gW1, const float* __restrict__ gb1,
              const float* __restrict__ gW2, const float* __restrict__ gb2,
              const float* __restrict__ gW3, const float* __restrict__ gb3,
              const float* __restrict__ gGw1, const float* __restrict__ gGb1,
              const float* __restrict__ gGw2, const float* __restrict__ gGb2,
              float* __restrict__ out)
{
    extern __shared__ float sm[];
    const int tid  = threadIdx.x;
    const int lane = tid & 31;
    const int warp = tid >> 5;
    const int bbase = blockIdx.x * (NW * WB) + warp * WB;

    // stage gating weights once (resident for whole kernel)
    copy_f4(sm + SGW1, gGw1, 1024, tid);
    copy_f4(sm + SGB1, gGb1,   16, tid);
    copy_f4(sm + SGW2, gGw2,  128, tid);
    copy_f4(sm + SGB2, gGb2,    2, tid);
    __syncthreads();

    float*  sInp = sm + SACT + warp * WARP_ACT;  // [33][8]
    float*  sHB  = sInp + OFF_H;                 // [64][8] h1/h2, then gin, gate-h, wgt
    __half* sFh  = (__half*)(sInp + OFF_F);      // [8][32][8] halfs (4 KB)

    float x[WB], xin[WB], ksum[WB];
    #pragma unroll
    for (int wb = 0; wb < WB; wb++){
        x[wb] = x0[(bbase + wb) * DDIM + lane];
        out[(bbase + wb) * (TPTS * DDIM) + lane] = x[wb];   // t = 0 row
    }

    #pragma unroll 1
    for (int s = 0; s < TPTS - 1; s++){
        const float t0 = tspan[s], t1 = tspan[s + 1];
        const float dt = t1 - t0;
        #pragma unroll
        for (int wb = 0; wb < WB; wb++){ xin[wb] = x[wb]; ksum[wb] = 0.f; }

        #pragma unroll 1
        for (int sub = 0; sub < 4; sub++){
            const float cc   = (sub == 0) ? 0.f : ((sub == 3) ? 1.f : 0.5f);
            const float tcur = fmaf(cc, dt, t0);

            // =================== dyn(tcur, xin) -> k ===================
            __syncwarp();
            *(float4*)(sInp + lane * 8)     = make_float4(xin[0], xin[1], xin[2], xin[3]);
            *(float4*)(sInp + lane * 8 + 4) = make_float4(xin[4], xin[5], xin[6], xin[7]);
            if (lane == 0){
                float4 tv = make_float4(tcur, tcur, tcur, tcur);
                *(float4*)(sInp + 32 * 8)     = tv;
                *(float4*)(sInp + 32 * 8 + 4) = tv;
            }
            __syncwarp();

            float dx[WB];
            #pragma unroll
            for (int wb = 0; wb < WB; wb++) dx[wb] = 0.f;

            #pragma unroll 1
            for (int e = 0; e < NEXP; e++){
                __syncthreads();   // all warps done with previous expert's weights
                copy_async(sm + SW1, gW1 + e * 2112, 528, tid);
                copy_async(sm + SB1, gb1 + e * 64,    16, tid);
                copy_async(sm + SW2, gW2 + e * 4096, 1024, tid);
                copy_async(sm + SB2, gb2 + e * 64,    16, tid);
                copy_async(sm + SW3, gW3 + e * 2048,  512, tid);
                copy_async(sm + SB3, gb3 + e * 32,     8, tid);
                asm volatile("cp.async.commit_group;");
                asm volatile("cp.async.wait_group 0;");
                __syncthreads();

                // ---- L1: h = tanh(inp @ W1e + b1e); lane owns cols lane, lane+32
                {
                    u64 acc[8];
                    #pragma unroll
                    for (int p = 0; p < 8; p++) acc[p] = 0ull;
                    #pragma unroll 4
                    for (int i = 0; i < 33; i++){
                        float w0 = sm[SW1 + i * 64 + lane];
                        float w1 = sm[SW1 + i * 64 + 32 + lane];
                        u64 w0p = pack2(w0, w0), w1p = pack2(w1, w1);
                        ROWMAC8(acc, sInp + i * 8, w0p, w1p);
                    }
                    float bl = sm[SB1 + lane], bh = sm[SB1 + 32 + lane];
                    float hv[16];
                    #pragma unroll
                    for (int p = 0; p < 4; p++){
                        float lo, hi;
                        unpack2(acc[p], lo, hi);
                        hv[2*p]     = tanh_fast(lo + bl); hv[2*p+1]   = tanh_fast(hi + bl);
                        unpack2(acc[4+p], lo, hi);
                        hv[8+2*p]   = tanh_fast(lo + bh); hv[8+2*p+1] = tanh_fast(hi + bh);
                    }
                    __syncwarp();
                    *(float4*)(sHB + lane * 8)            = make_float4(hv[0], hv[1], hv[2], hv[3]);
                    *(float4*)(sHB + lane * 8 + 4)        = make_float4(hv[4], hv[5], hv[6], hv[7]);
                    *(float4*)(sHB + (lane + 32) * 8)     = make_float4(hv[8], hv[9], hv[10], hv[11]);
                    *(float4*)(sHB + (lane + 32) * 8 + 4) = make_float4(hv[12], hv[13], hv[14], hv[15]);
                    __syncwarp();
                }

                // ---- L2: h = tanh(h @ W2e + b2e)
                {
                    u64 acc[8];
                    #pragma unroll
                    for (int p = 0; p < 8; p++) acc[p] = 0ull;
                    #pragma unroll 4
                    for (int i = 0; i < 64; i++){
                        float w0 = sm[SW2 + i * 64 + lane];
                        float w1 = sm[SW2 + i * 64 + 32 + lane];
                        u64 w0p = pack2(w0, w0), w1p = pack2(w1, w1);
                        ROWMAC8(acc, sHB + i * 8, w0p, w1p);
                    }
                    float bl = sm[SB2 + lane], bh = sm[SB2 + 32 + lane];
                    float hv[16];
                    #pragma unroll
                    for (int p = 0; p < 4; p++){
                        float lo, hi;
                        unpack2(acc[p], lo, hi);
                        hv[2*p]     = tanh_fast(lo + bl); hv[2*p+1]   = tanh_fast(hi + bl);
                        unpack2(acc[4+p], lo, hi);
                        hv[8+2*p]   = tanh_fast(lo + bh); hv[8+2*p+1] = tanh_fast(hi + bh);
                    }
                    __syncwarp();   // all lanes done reading sHB
                    *(float4*)(sHB + lane * 8)            = make_float4(hv[0], hv[1], hv[2], hv[3]);
                    *(float4*)(sHB + lane * 8 + 4)        = make_float4(hv[4], hv[5], hv[6], hv[7]);
                    *(float4*)(sHB + (lane + 32) * 8)     = make_float4(hv[8], hv[9], hv[10], hv[11]);
                    *(float4*)(sHB + (lane + 32) * 8 + 4) = make_float4(hv[12], hv[13], hv[14], hv[15]);
                    __syncwarp();
                }

                // ---- L3: f = h @ W3e + b3e ; lane owns col d = lane; store fp16
                {
                    u64 a3[4];
                    #pragma unroll
                    for (int p = 0; p < 4; p++) a3[p] = 0ull;
                    #pragma unroll 4
                    for (int kk = 0; kk < 64; kk++){
                        float w = sm[SW3 + kk * 32 + lane];
                        u64 wp = pack2(w, w);
                        ulonglong2 a0 = *(const ulonglong2*)(sHB + kk * 8);
                        ulonglong2 a1 = *(const ulonglong2*)(sHB + kk * 8 + 4);
                        a3[0] = ffma2(wp, a0.x, a3[0]); a3[1] = ffma2(wp, a0.y, a3[1]);
                        a3[2] = ffma2(wp, a1.x, a3[2]); a3[3] = ffma2(wp, a1.y, a3[3]);
                    }
                    float b3v = sm[SB3 + lane];
                    float fv[8];
                    #pragma unroll
                    for (int p = 0; p < 4; p++){
                        float lo, hi; unpack2(a3[p], lo, hi);
                        fv[2*p] = lo + b3v; fv[2*p+1] = hi + b3v;
                    }
                    __half2 h0 = __floats2half2_rn(fv[0], fv[1]);
                    __half2 h1 = __floats2half2_rn(fv[2], fv[3]);
                    __half2 h2 = __floats2half2_rn(fv[4], fv[5]);
                    __half2 h3 = __floats2half2_rn(fv[6], fv[7]);
                    uint4 pk;
                    pk.x = *(u32*)&h0; pk.y = *(u32*)&h1; pk.z = *(u32*)&h2; pk.w = *(u32*)&h3;
                    ((uint4*)sFh)[e * 32 + lane] = pk;
                    #pragma unroll
                    for (int wb = 0; wb < WB; wb++) dx[wb] += fv[wb];
                }
            } // expert loop

            // ---- gating: gin = concat(xin, mean_e f) in sHB (h2 dead) ----
            *(float4*)(sHB + lane * 8)            = make_float4(xin[0], xin[1], xin[2], xin[3]);
            *(float4*)(sHB + lane * 8 + 4)        = make_float4(xin[4], xin[5], xin[6], xin[7]);
            *(float4*)(sHB + (lane + 32) * 8)     = make_float4(dx[0]*0.125f, dx[1]*0.125f, dx[2]*0.125f, dx[3]*0.125f);
            *(float4*)(sHB + (lane + 32) * 8 + 4) = make_float4(dx[4]*0.125f, dx[5]*0.125f, dx[6]*0.125f, dx[7]*0.125f);
            __syncwarp();
            {
                u64 ag[8];
                #pragma unroll
                for (int p = 0; p < 8; p++) ag[p] = 0ull;
                #pragma unroll 4
                for (int i = 0; i < 64; i++){
                    float w0 = sm[SGW1 + i * 64 + lane];
                    float w1 = sm[SGW1 + i * 64 + 32 + lane];
                    u64 w0p = pack2(w0, w0), w1p = pack2(w1, w1);
                    ROWMAC8(ag, sHB + i * 8, w0p, w1p);
                }
                float bl = sm[SGB1 + lane], bh = sm[SGB1 + 32 + lane];
                float gv[16];
                #pragma unroll
                for (int p = 0; p < 4; p++){
                    float lo, hi;
                    unpack2(ag[p], lo, hi);
                    gv[2*p]     = tanh_fast(lo + bl); gv[2*p+1]   = tanh_fast(hi + bl);
                    unpack2(ag[4+p], lo, hi);
                    gv[8+2*p]   = tanh_fast(lo + bh); gv[8+2*p+1] = tanh_fast(hi + bh);
                }
                __syncwarp();   // gin fully consumed
                *(float4*)(sHB + lane * 8)            = make_float4(gv[0], gv[1], gv[2], gv[3]);
                *(float4*)(sHB + lane * 8 + 4)        = make_float4(gv[4], gv[5], gv[6], gv[7]);
                *(float4*)(sHB + (lane + 32) * 8)     = make_float4(gv[8], gv[9], gv[10], gv[11]);
                *(float4*)(sHB + (lane + 32) * 8 + 4) = make_float4(gv[12], gv[13], gv[14], gv[15]);
                __syncwarp();
            }
            // ---- logits + softmax: lane = expert ep x quarter q of H
            float wgt[WB];
            {
                const int ep = lane & 7, q = lane >> 3;
                u64 z2[4];
                #pragma unroll
                for (int p = 0; p < 4; p++) z2[p] = 0ull;
                #pragma unroll 4
                for (int r = 0; r < 16; r++){
                    int j = q * 16 + r;
                    float w = sm[SGW2 + j * 8 + ep];
                    u64 wp = pack2(w, w);
                    ulonglong2 a0 = *(const ulonglong2*)(sHB + j * 8);
                    ulonglong2 a1 = *(const ulonglong2*)(sHB + j * 8 + 4);
                    z2[0] = ffma2(wp, a0.x, z2[0]); z2[1] = ffma2(wp, a0.y, z2[1]);
                    z2[2] = ffma2(wp, a1.x, z2[2]); z2[3] = ffma2(wp, a1.y, z2[3]);
                }
                float z[WB];
                #pragma unroll
                for (int p = 0; p < 4; p++){ unpack2(z2[p], z[2*p], z[2*p+1]); }
                float gb2v = sm[SGB2 + ep];
                #pragma unroll
                for (int v = 0; v < WB; v++){
                    z[v] += __shfl_xor_sync(0xffffffffu, z[v], 8);
                    z[v] += __shfl_xor_sync(0xffffffffu, z[v], 16);
                    z[v] += gb2v;
                    float m = z[v];
                    m = fmaxf(m, __shfl_xor_sync(0xffffffffu, m, 1));
                    m = fmaxf(m, __shfl_xor_sync(0xffffffffu, m, 2));
                    m = fmaxf(m, __shfl_xor_sync(0xffffffffu, m, 4));
                    float p = exp_fast(z[v] - m);
                    float ss = p;
                    ss += __shfl_xor_sync(0xffffffffu, ss, 1);
                    ss += __shfl_xor_sync(0xffffffffu, ss, 2);
                    ss += __shfl_xor_sync(0xffffffffu, ss, 4);
                    wgt[v] = p * rcp_fast(ss);
                }
            }
            __syncwarp();   // gate-h consumed
            if (lane < 8){  // q==0 lanes publish wgt[e=lane][wb]
                *(float4*)(sHB + lane * 8)     = make_float4(wgt[0], wgt[1], wgt[2], wgt[3]);
                *(float4*)(sHB + lane * 8 + 4) = make_float4(wgt[4], wgt[5], wgt[6], wgt[7]);
            }
            __syncwarp();

            // ---- k = sum_e wgt[e] * f[e] (f in fp16)
            float k[WB];
            #pragma unroll
            for (int wb = 0; wb < WB; wb++) k[wb] = 0.f;
            #pragma unroll
            for (int e2 = 0; e2 < NEXP; e2++){
                float4 wa = *(const float4*)(sHB + e2 * 8);
                float4 wv = *(const float4*)(sHB + e2 * 8 + 4);
                uint4 pk = ((const uint4*)sFh)[e2 * 32 + lane];
                float2 f01 = __half22float2(*(__half2*)&pk.x);
                float2 f23 = __half22float2(*(__half2*)&pk.y);
                float2 f45 = __half22float2(*(__half2*)&pk.z);
                float2 f67 = __half22float2(*(__half2*)&pk.w);
                k[0] = fmaf(wa.x, f01.x, k[0]); k[1] = fmaf(wa.y, f01.y, k[1]);
                k[2] = fmaf(wa.z, f23.x, k[2]); k[3] = fmaf(wa.w, f23.y, k[3]);
                k[4] = fmaf(wv.x, f45.x, k[4]); k[5] = fmaf(wv.y, f45.y, k[5]);
                k[6] = fmaf(wv.z, f67.x, k[6]); k[7] = fmaf(wv.w, f67.y, k[7]);
            }
            // =================== end dyn ===================

            const float wsum = (sub == 0 || sub == 3) ? 1.f : 2.f;
            #pragma unroll
            for (int wb = 0; wb < WB; wb++) ksum[wb] = fmaf(wsum, k[wb], ksum[wb]);
            if (sub < 3){
                const float nc = (sub == 2) ? dt : 0.5f * dt;
                #pragma unroll
                for (int wb = 0; wb < WB; wb++) xin[wb] = fmaf(nc, k[wb], x[wb]);
            }
        } // sub

        const float sc = dt * (1.0f / 6.0f);
        #pragma unroll
        for (int wb = 0; wb < WB; wb++){
            x[wb] = fmaf(sc, ksum[wb], x[wb]);
            out[(bbase + wb) * (TPTS * DDIM) + (s + 1) * DDIM + lane] = x[wb];
        }
    } // step
}

extern "C" void kernel_launch(void* const* d_in, const int* in_sizes, int n_in,
                              void* d_out, int out_size)
{
    (void)in_sizes; (void)n_in; (void)out_size;
    cudaFuncSetAttribute(ameode_kernel, cudaFuncAttributeMaxDynamicSharedMemorySize, SMEM_BYTES);
    ameode_kernel<<<256, CTA_THREADS, SMEM_BYTES>>>(
        (const float*)d_in[0],  (const float*)d_in[1],
        (const float*)d_in[2],  (const float*)d_in[3],
        (const float*)d_in[4],  (const float*)d_in[5],
        (const float*)d_in[6],  (const float*)d_in[7],
        (const float*)d_in[8],  (const float*)d_in[9],
        (const float*)d_in[10], (const float*)d_in[11],
        (float*)d_out);
}

// round 7
// speedup vs baseline: 1.5024x; 1.0665x over previous
#include <cuda_runtime.h>
#include <cuda_fp16.h>

typedef unsigned long long u64;
typedef unsigned int u32;

#define WB 8
#define NW 16
#define CTA_THREADS 512
#define TPTS 10
#define DDIM 32
#define NEXP 8

// ---- shared memory layout (float offsets) ----
// two expert weight buffers (ring), each 8416 floats:
//   W1 0 | b1 2112 | W2 2176 | b2 6272 | W3 6336 | b3 8384
#define EXPBUF 8416
#define SGW1  16832      // 4096
#define SGB1  20928      // 64
#define SGW2  20992      // 512
#define SGB2  21504      // 8
#define SACT  21512
// per-warp activation region (WB=8): inp 264 | hbuf 512 | f(half) 1024 float-equiv
#define OFF_H   264
#define OFF_F   776
#define WARP_ACT 1800
#define SMEM_BYTES ((SACT + NW * WARP_ACT) * 4)   // 201248 bytes, 1 CTA/SM

// offsets inside an expert buffer
#define OW1 0
#define OB1 2112
#define OW2 2176
#define OB2 6272
#define OW3 6336
#define OB3 8384

static __device__ __forceinline__ u64 pack2(float lo, float hi){
    u64 r; asm("mov.b64 %0,{%1,%2};" : "=l"(r) : "f"(lo), "f"(hi)); return r;
}
static __device__ __forceinline__ void unpack2(u64 v, float &lo, float &hi){
    asm("mov.b64 {%0,%1},%2;" : "=f"(lo), "=f"(hi) : "l"(v));
}
static __device__ __forceinline__ u64 ffma2(u64 a, u64 b, u64 c){
    u64 d; asm("fma.rn.f32x2 %0,%1,%2,%3;" : "=l"(d) : "l"(a), "l"(b), "l"(c)); return d;
}
static __device__ __forceinline__ float tanh_fast(float x){
    float e, r;
    asm("ex2.approx.f32 %0,%1;" : "=f"(e) : "f"(x * 2.8853900817779268f));
    asm("rcp.approx.f32 %0,%1;" : "=f"(r) : "f"(e + 1.0f));
    return fmaf(-2.0f, r, 1.0f);
}
static __device__ __forceinline__ float exp_fast(float x){
    float e; asm("ex2.approx.f32 %0,%1;" : "=f"(e) : "f"(x * 1.4426950408889634f)); return e;
}
static __device__ __forceinline__ float rcp_fast(float x){
    float r; asm("rcp.approx.f32 %0,%1;" : "=f"(r) : "f"(x)); return r;
}

static __device__ __forceinline__ void cp16(u32 dst_smem, const float4* src){
    asm volatile("cp.async.cg.shared.global [%0],[%1],16;" :: "r"(dst_smem), "l"(src));
}
static __device__ __forceinline__ void copy_async(float* dst, const float* __restrict__ src,
                                                  int n4, int tid){
    u32 d = (u32)__cvta_generic_to_shared(dst);
    const float4* s = (const float4*)src;
    for (int i = tid; i < n4; i += CTA_THREADS) cp16(d + i * 16, s + i);
}
static __device__ __forceinline__ void copy_f4(float* dst, const float* __restrict__ src,
                                               int n4, int tid){
    const float4* s = (const float4*)src;
    float4* d = (float4*)dst;
    for (int i = tid; i < n4; i += CTA_THREADS) d[i] = s[i];
}

// row-MAC (WB=8): 8 f32x2 accumulators (cols lane / lane+32, 4 batch pairs)
#define ROWMAC8(acc, rowptr, w0p, w1p) { \
    ulonglong2 a0_ = *(const ulonglong2*)(rowptr); \
    ulonglong2 a1_ = *(const ulonglong2*)((rowptr) + 4); \
    acc[0] = ffma2(w0p, a0_.x, acc[0]); acc[1] = ffma2(w0p, a0_.y, acc[1]); \
    acc[2] = ffma2(w0p, a1_.x, acc[2]); acc[3] = ffma2(w0p, a1_.y, acc[3]); \
    acc[4] = ffma2(w1p, a0_.x, acc[4]); acc[5] = ffma2(w1p, a0_.y, acc[5]); \
    acc[6] = ffma2(w1p, a1_.x, acc[6]); acc[7] = ffma2(w1p, a1_.y, acc[7]); }

struct WPtrs {
    const float *gW1, *gb1, *gW2, *gb2, *gW3, *gb3;
};

static __device__ __forceinline__ void stage_expert(float* buf, const WPtrs& g, int e, int tid){
    copy_async(buf + OW1, g.gW1 + e * 2112, 528, tid);
    copy_async(buf + OB1, g.gb1 + e * 64,    16, tid);
    copy_async(buf + OW2, g.gW2 + e * 4096, 1024, tid);
    copy_async(buf + OB2, g.gb2 + e * 64,    16, tid);
    copy_async(buf + OW3, g.gW3 + e * 2048,  512, tid);
    copy_async(buf + OB3, g.gb3 + e * 32,     8, tid);
    asm volatile("cp.async.commit_group;");
}

__global__ void __launch_bounds__(CTA_THREADS, 1)
ameode_kernel(const float* __restrict__ x0,  const float* __restrict__ tspan,
              const float* __restrict__ gW1, const float* __restrict__ gb1,
              const float* __restrict__ gW2, const float* __restrict__ gb2,
              const float* __restrict__ gW3, const float* __restrict__ gb3,
              const float* __restrict__ gGw1, const float* __restrict__ gGb1,
              const float* __restrict__ gGw2, const float* __restrict__ gGb2,
              float* __restrict__ out)
{
    extern __shared__ float sm[];
    const int tid  = threadIdx.x;
    const int lane = tid & 31;
    const int warp = tid >> 5;
    const int bbase = blockIdx.x * (NW * WB) + warp * WB;

    WPtrs g; g.gW1 = gW1; g.gb1 = gb1; g.gW2 = gW2; g.gb2 = gb2; g.gW3 = gW3; g.gb3 = gb3;

    // stage gating weights once (resident for whole kernel)
    copy_f4(sm + SGW1, gGw1, 1024, tid);
    copy_f4(sm + SGB1, gGb1,   16, tid);
    copy_f4(sm + SGW2, gGw2,  128, tid);
    copy_f4(sm + SGB2, gGb2,    2, tid);
    // prime the ring with expert 0
    stage_expert(sm, g, 0, tid);

    float*  sInp = sm + SACT + warp * WARP_ACT;  // [33][8]
    float*  sHB  = sInp + OFF_H;                 // [64][8] h1/h2, gin, gate-h, wgt
    __half* sFh  = (__half*)(sInp + OFF_F);      // [8][32][8] halfs (4 KB)

    float x[WB], xin[WB], ksum[WB];
    #pragma unroll
    for (int wb = 0; wb < WB; wb++){
        x[wb] = x0[(bbase + wb) * DDIM + lane];
        out[(bbase + wb) * (TPTS * DDIM) + lane] = x[wb];   // t = 0 row
    }

    #pragma unroll 1
    for (int s = 0; s < TPTS - 1; s++){
        const float t0 = tspan[s], t1 = tspan[s + 1];
        const float dt = t1 - t0;
        #pragma unroll
        for (int wb = 0; wb < WB; wb++){ xin[wb] = x[wb]; ksum[wb] = 0.f; }

        #pragma unroll 1
        for (int sub = 0; sub < 4; sub++){
            const float cc   = (sub == 0) ? 0.f : ((sub == 3) ? 1.f : 0.5f);
            const float tcur = fmaf(cc, dt, t0);

            // =================== dyn(tcur, xin) -> k ===================
            __syncwarp();
            *(float4*)(sInp + lane * 8)     = make_float4(xin[0], xin[1], xin[2], xin[3]);
            *(float4*)(sInp + lane * 8 + 4) = make_float4(xin[4], xin[5], xin[6], xin[7]);
            if (lane == 0){
                float4 tv = make_float4(tcur, tcur, tcur, tcur);
                *(float4*)(sInp + 32 * 8)     = tv;
                *(float4*)(sInp + 32 * 8 + 4) = tv;
            }
            __syncwarp();

            float dx[WB];
            #pragma unroll
            for (int wb = 0; wb < WB; wb++) dx[wb] = 0.f;

            #pragma unroll 1
            for (int e = 0; e < NEXP; e++){
                // expert e's weights were prefetched last iteration (or pre-loop)
                asm volatile("cp.async.wait_group 0;");
                __syncthreads();   // RAW: e visible to all; WAR: all done with e-1's buffer
                stage_expert(sm + (((e + 1) & 1) * EXPBUF), g, (e + 1) & 7, tid);
                const float* W = sm + ((e & 1) * EXPBUF);

                // ---- L1: h = tanh(inp @ W1e + b1e); lane owns cols lane, lane+32
                {
                    u64 acc[8];
                    #pragma unroll
                    for (int p = 0; p < 8; p++) acc[p] = 0ull;
                    #pragma unroll 8
                    for (int i = 0; i < 32; i++){
                        float w0 = W[OW1 + i * 64 + lane];
                        float w1 = W[OW1 + i * 64 + 32 + lane];
                        u64 w0p = pack2(w0, w0), w1p = pack2(w1, w1);
                        ROWMAC8(acc, sInp + i * 8, w0p, w1p);
                    }
                    {   // t row (i = 32)
                        float w0 = W[OW1 + 32 * 64 + lane];
                        float w1 = W[OW1 + 32 * 64 + 32 + lane];
                        u64 w0p = pack2(w0, w0), w1p = pack2(w1, w1);
                        ROWMAC8(acc, sInp + 32 * 8, w0p, w1p);
                    }
                    float bl = W[OB1 + lane], bh = W[OB1 + 32 + lane];
                    float hv[16];
                    #pragma unroll
                    for (int p = 0; p < 4; p++){
                        float lo, hi;
                        unpack2(acc[p], lo, hi);
                        hv[2*p]     = tanh_fast(lo + bl); hv[2*p+1]   = tanh_fast(hi + bl);
                        unpack2(acc[4+p], lo, hi);
                        hv[8+2*p]   = tanh_fast(lo + bh); hv[8+2*p+1] = tanh_fast(hi + bh);
                    }
                    __syncwarp();
                    *(float4*)(sHB + lane * 8)            = make_float4(hv[0], hv[1], hv[2], hv[3]);
                    *(float4*)(sHB + lane * 8 + 4)        = make_float4(hv[4], hv[5], hv[6], hv[7]);
                    *(float4*)(sHB + (lane + 32) * 8)     = make_float4(hv[8], hv[9], hv[10], hv[11]);
                    *(float4*)(sHB + (lane + 32) * 8 + 4) = make_float4(hv[12], hv[13], hv[14], hv[15]);
                    __syncwarp();
                }

                // ---- L2: h = tanh(h @ W2e + b2e)
                {
                    u64 acc[8];
                    #pragma unroll
                    for (int p = 0; p < 8; p++) acc[p] = 0ull;
                    #pragma unroll 8
                    for (int i = 0; i < 64; i++){
                        float w0 = W[OW2 + i * 64 + lane];
                        float w1 = W[OW2 + i * 64 + 32 + lane];
                        u64 w0p = pack2(w0, w0), w1p = pack2(w1, w1);
                        ROWMAC8(acc, sHB + i * 8, w0p, w1p);
                    }
                    float bl = W[OB2 + lane], bh = W[OB2 + 32 + lane];
                    float hv[16];
                    #pragma unroll
                    for (int p = 0; p < 4; p++){
                        float lo, hi;
                        unpack2(acc[p], lo, hi);
                        hv[2*p]     = tanh_fast(lo + bl); hv[2*p+1]   = tanh_fast(hi + bl);
                        unpack2(acc[4+p], lo, hi);
                        hv[8+2*p]   = tanh_fast(lo + bh); hv[8+2*p+1] = tanh_fast(hi + bh);
                    }
                    __syncwarp();   // all lanes done reading sHB
                    *(float4*)(sHB + lane * 8)            = make_float4(hv[0], hv[1], hv[2], hv[3]);
                    *(float4*)(sHB + lane * 8 + 4)        = make_float4(hv[4], hv[5], hv[6], hv[7]);
                    *(float4*)(sHB + (lane + 32) * 8)     = make_float4(hv[8], hv[9], hv[10], hv[11]);
                    *(float4*)(sHB + (lane + 32) * 8 + 4) = make_float4(hv[12], hv[13], hv[14], hv[15]);
                    __syncwarp();
                }

                // ---- L3: f = h @ W3e + b3e ; lane owns col d = lane; store fp16
                {
                    u64 a3[4];
                    #pragma unroll
                    for (int p = 0; p < 4; p++) a3[p] = 0ull;
                    #pragma unroll 8
                    for (int kk = 0; kk < 64; kk++){
                        float w = W[OW3 + kk * 32 + lane];
                        u64 wp = pack2(w, w);
                        ulonglong2 a0 = *(const ulonglong2*)(sHB + kk * 8);
                        ulonglong2 a1 = *(const ulonglong2*)(sHB + kk * 8 + 4);
                        a3[0] = ffma2(wp, a0.x, a3[0]); a3[1] = ffma2(wp, a0.y, a3[1]);
                        a3[2] = ffma2(wp, a1.x, a3[2]); a3[3] = ffma2(wp, a1.y, a3[3]);
                    }
                    float b3v = W[OB3 + lane];
                    float fv[8];
                    #pragma unroll
                    for (int p = 0; p < 4; p++){
                        float lo, hi; unpack2(a3[p], lo, hi);
                        fv[2*p] = lo + b3v; fv[2*p+1] = hi + b3v;
                    }
                    __half2 h0 = __floats2half2_rn(fv[0], fv[1]);
                    __half2 h1 = __floats2half2_rn(fv[2], fv[3]);
                    __half2 h2 = __floats2half2_rn(fv[4], fv[5]);
                    __half2 h3 = __floats2half2_rn(fv[6], fv[7]);
                    uint4 pk;
                    pk.x = *(u32*)&h0; pk.y = *(u32*)&h1; pk.z = *(u32*)&h2; pk.w = *(u32*)&h3;
                    ((uint4*)sFh)[e * 32 + lane] = pk;
                    #pragma unroll
                    for (int wb = 0; wb < WB; wb++) dx[wb] += fv[wb];
                }
            } // expert loop  (next eval's expert 0 prefetch overlaps gating below)

            // ---- gating: gin = concat(xin, mean_e f) in sHB ----
            *(float4*)(sHB + lane * 8)            = make_float4(xin[0], xin[1], xin[2], xin[3]);
            *(float4*)(sHB + lane * 8 + 4)        = make_float4(xin[4], xin[5], xin[6], xin[7]);
            *(float4*)(sHB + (lane + 32) * 8)     = make_float4(dx[0]*0.125f, dx[1]*0.125f, dx[2]*0.125f, dx[3]*0.125f);
            *(float4*)(sHB + (lane + 32) * 8 + 4) = make_float4(dx[4]*0.125f, dx[5]*0.125f, dx[6]*0.125f, dx[7]*0.125f);
            __syncwarp();
            {
                u64 ag[8];
                #pragma unroll
                for (int p = 0; p < 8; p++) ag[p] = 0ull;
                #pragma unroll 8
                for (int i = 0; i < 64; i++){
                    float w0 = sm[SGW1 + i * 64 + lane];
                    float w1 = sm[SGW1 + i * 64 + 32 + lane];
                    u64 w0p = pack2(w0, w0), w1p = pack2(w1, w1);
                    ROWMAC8(ag, sHB + i * 8, w0p, w1p);
                }
                float bl = sm[SGB1 + lane], bh = sm[SGB1 + 32 + lane];
                float gv[16];
                #pragma unroll
                for (int p = 0; p < 4; p++){
                    float lo, hi;
                    unpack2(ag[p], lo, hi);
                    gv[2*p]     = tanh_fast(lo + bl); gv[2*p+1]   = tanh_fast(hi + bl);
                    unpack2(ag[4+p], lo, hi);
                    gv[8+2*p]   = tanh_fast(lo + bh); gv[8+2*p+1] = tanh_fast(hi + bh);
                }
                __syncwarp();   // gin fully consumed
                *(float4*)(sHB + lane * 8)            = make_float4(gv[0], gv[1], gv[2], gv[3]);
                *(float4*)(sHB + lane * 8 + 4)        = make_float4(gv[4], gv[5], gv[6], gv[7]);
                *(float4*)(sHB + (lane + 32) * 8)     = make_float4(gv[8], gv[9], gv[10], gv[11]);
                *(float4*)(sHB + (lane + 32) * 8 + 4) = make_float4(gv[12], gv[13], gv[14], gv[15]);
                __syncwarp();
            }
            // ---- logits + softmax: lane = expert ep x quarter q of H
            float wgt[WB];
            {
                const int ep = lane & 7, q = lane >> 3;
                u64 z2[4];
                #pragma unroll
                for (int p = 0; p < 4; p++) z2[p] = 0ull;
                #pragma unroll 4
                for (int r = 0; r < 16; r++){
                    int j = q * 16 + r;
                    float w = sm[SGW2 + j * 8 + ep];
                    u64 wp = pack2(w, w);
                    ulonglong2 a0 = *(const ulonglong2*)(sHB + j * 8);
                    ulonglong2 a1 = *(const ulonglong2*)(sHB + j * 8 + 4);
                    z2[0] = ffma2(wp, a0.x, z2[0]); z2[1] = ffma2(wp, a0.y, z2[1]);
                    z2[2] = ffma2(wp, a1.x, z2[2]); z2[3] = ffma2(wp, a1.y, z2[3]);
                }
                float z[WB];
                #pragma unroll
                for (int p = 0; p < 4; p++){ unpack2(z2[p], z[2*p], z[2*p+1]); }
                float gb2v = sm[SGB2 + ep];
                #pragma unroll
                for (int v = 0; v < WB; v++){
                    z[v] += __shfl_xor_sync(0xffffffffu, z[v], 8);
                    z[v] += __shfl_xor_sync(0xffffffffu, z[v], 16);
                    z[v] += gb2v;
                    float m = z[v];
                    m = fmaxf(m, __shfl_xor_sync(0xffffffffu, m, 1));
                    m = fmaxf(m, __shfl_xor_sync(0xffffffffu, m, 2));
                    m = fmaxf(m, __shfl_xor_sync(0xffffffffu, m, 4));
                    float p = exp_fast(z[v] - m);
                    float ss = p;
                    ss += __shfl_xor_sync(0xffffffffu, ss, 1);
                    ss += __shfl_xor_sync(0xffffffffu, ss, 2);
                    ss += __shfl_xor_sync(0xffffffffu, ss, 4);
                    wgt[v] = p * rcp_fast(ss);
                }
            }
            __syncwarp();   // gate-h consumed
            if (lane < 8){  // q==0 lanes publish wgt[e=lane][wb]
                *(float4*)(sHB + lane * 8)     = make_float4(wgt[0], wgt[1], wgt[2], wgt[3]);
                *(float4*)(sHB + lane * 8 + 4) = make_float4(wgt[4], wgt[5], wgt[6], wgt[7]);
            }
            __syncwarp();

            // ---- k = sum_e wgt[e] * f[e] (f in fp16)
            float k[WB];
            #pragma unroll
            for (int wb = 0; wb < WB; wb++) k[wb] = 0.f;
            #pragma unroll
            for (int e2 = 0; e2 < NEXP; e2++){
                float4 wa = *(const float4*)(sHB + e2 * 8);
                float4 wv = *(const float4*)(sHB + e2 * 8 + 4);
                uint4 pk = ((const uint4*)sFh)[e2 * 32 + lane];
                float2 f01 = __half22float2(*(__half2*)&pk.x);
                float2 f23 = __half22float2(*(__half2*)&pk.y);
                float2 f45 = __half22float2(*(__half2*)&pk.z);
                float2 f67 = __half22float2(*(__half2*)&pk.w);
                k[0] = fmaf(wa.x, f01.x, k[0]); k[1] = fmaf(wa.y, f01.y, k[1]);
                k[2] = fmaf(wa.z, f23.x, k[2]); k[3] = fmaf(wa.w, f23.y, k[3]);
                k[4] = fmaf(wv.x, f45.x, k[4]); k[5] = fmaf(wv.y, f45.y, k[5]);
                k[6] = fmaf(wv.z, f67.x, k[6]); k[7] = fmaf(wv.w, f67.y, k[7]);
            }
            // =================== end dyn ===================

            const float wsum = (sub == 0 || sub == 3) ? 1.f : 2.f;
            #pragma unroll
            for (int wb = 0; wb < WB; wb++) ksum[wb] = fmaf(wsum, k[wb], ksum[wb]);
            if (sub < 3){
                const float nc = (sub == 2) ? dt : 0.5f * dt;
                #pragma unroll
                for (int wb = 0; wb < WB; wb++) xin[wb] = fmaf(nc, k[wb], x[wb]);
            }
        } // sub

        const float sc = dt * (1.0f / 6.0f);
        #pragma unroll
        for (int wb = 0; wb < WB; wb++){
            x[wb] = fmaf(sc, ksum[wb], x[wb]);
            out[(bbase + wb) * (TPTS * DDIM) + (s + 1) * DDIM + lane] = x[wb];
        }
    } // step
}

extern "C" void kernel_launch(void* const* d_in, const int* in_sizes, int n_in,
                              void* d_out, int out_size)
{
    (void)in_sizes; (void)n_in; (void)out_size;
    cudaFuncSetAttribute(ameode_kernel, cudaFuncAttributeMaxDynamicSharedMemorySize, SMEM_BYTES);
    ameode_kernel<<<128, CTA_THREADS, SMEM_BYTES>>>(
        (const float*)d_in[0],  (const float*)d_in[1],
        (const float*)d_in[2],  (const float*)d_in[3],
        (const float*)d_in[4],  (const float*)d_in[5],
        (const float*)d_in[6],  (const float*)d_in[7],
        (const float*)d_in[8],  (const float*)d_in[9],
        (const float*)d_in[10], (const float*)d_in[11],
        (float*)d_out);
}